// round 14
// baseline (speedup 1.0000x reference)
#include <cuda_runtime.h>
#include <cuda_fp16.h>
#include <math.h>
#include <stdint.h>

// ---------------- Problem constants ----------------
#define DIM   128
#define E_MAX 100000
#define P_MAX 800000
#define G_MAX 1000
#define TSTEPS 8

// ---------------- Device scratch (no allocations allowed) ----------------
__device__ float d_h  [E_MAX * DIM];
__device__ float d_agg[E_MAX * DIM];
__device__ float d_UV [E_MAX * 256];
__device__ float d_X1 [E_MAX * 384];
__device__ float d_X2 [E_MAX * 384];
__device__ float d_pool[G_MAX * DIM];
__device__ float d_r1 [G_MAX * 256];
__device__ float d_r2 [G_MAX * 256];
__device__ float d_b256[256];          // [0..127]=0, [128..255]=b_msg
// split+transposed weights: rows 0..383 = gru_kernel^T, 384..767 = gru_rec^T, 768..1023 = Wuv^T
__device__ __half d_WtHi[1024 * 128];
__device__ __half d_WtLo[1024 * 128];
// CSR grouping of pairs by `second`
__device__ int d_off   [E_MAX + 1];
__device__ int d_cur   [E_MAX];
__device__ int d_pfirst[P_MAX];
__device__ int d_blk   [256];

// ---------------- math helpers ----------------
__device__ __forceinline__ float selu_f(float x) {
    const float sc = 1.0507009873554805f;
    const float al = 1.6732632423543772f;
    return x > 0.f ? sc * x : sc * al * (expf(x) - 1.f);
}
__device__ __forceinline__ float sigmoid_f(float x) { return 1.f / (1.f + expf(-x)); }

__device__ __forceinline__ uint32_t smem_u32(const void* p) {
    uint32_t a;
    asm("{ .reg .u64 t; cvta.to.shared.u64 t, %1; cvt.u32.u64 %0, t; }" : "=r"(a) : "l"(p));
    return a;
}

#define CP_ASYNC16(dst, src) \
    asm volatile("cp.async.cg.shared.global [%0], [%1], 16;" :: "r"(dst), "l"(src))
#define CP_COMMIT() asm volatile("cp.async.commit_group;" ::: "memory")
#define CP_WAIT0()  asm volatile("cp.async.wait_group 0;" ::: "memory")

// swizzled byte offset of 16B chunk c8 (0..15) in row r (256B rows)
__device__ __forceinline__ uint32_t sw_off(int r, int c8) {
    return ((uint32_t)r << 8) + (uint32_t)((c8 ^ (r & 7)) << 4);
}

__device__ __forceinline__ void ldsm_x4(uint32_t addr, uint32_t* r) {
    asm volatile("ldmatrix.sync.aligned.m8n8.x4.shared.b16 {%0,%1,%2,%3}, [%4];"
                 : "=r"(r[0]), "=r"(r[1]), "=r"(r[2]), "=r"(r[3]) : "r"(addr));
}

__device__ __forceinline__ void mma16816(float* c, const uint32_t* a, uint32_t b0, uint32_t b1) {
    asm volatile(
        "mma.sync.aligned.m16n8k16.row.col.f32.f16.f16.f32 "
        "{%0,%1,%2,%3}, {%4,%5,%6,%7}, {%8,%9}, {%0,%1,%2,%3};"
        : "+f"(c[0]), "+f"(c[1]), "+f"(c[2]), "+f"(c[3])
        : "r"(a[0]), "r"(a[1]), "r"(a[2]), "r"(a[3]), "r"(b0), "r"(b1));
}

// split fp32 float4 into fp16 hi/lo pairs packed as uint2
__device__ __forceinline__ void split4(float4 v, uint2& hu, uint2& lu) {
    __half2 h01 = __floats2half2_rn(v.x, v.y);
    __half2 h23 = __floats2half2_rn(v.z, v.w);
    float lx = v.x - __half2float(__low2half(h01));
    float ly = v.y - __half2float(__high2half(h01));
    float lz = v.z - __half2float(__low2half(h23));
    float lw = v.w - __half2float(__high2half(h23));
    __half2 l01 = __floats2half2_rn(lx, ly);
    __half2 l23 = __floats2half2_rn(lz, lw);
    hu.x = *(uint32_t*)&h01; hu.y = *(uint32_t*)&h23;
    lu.x = *(uint32_t*)&l01; lu.y = *(uint32_t*)&l23;
}

// ---------------- Weight prep ----------------
__global__ void prep_weights(const float* __restrict__ gru_k, const float* __restrict__ gru_rk,
                             const float* __restrict__ W_msg, const float* __restrict__ b_msg,
                             __half* __restrict__ WtHi, __half* __restrict__ WtLo,
                             float* __restrict__ b256)
{
    int i = blockIdx.x * blockDim.x + threadIdx.x;
    if (i >= 1024 * 128) return;
    if (i < 256) b256[i] = (i < 128) ? 0.f : b_msg[i - 128];
    int n = i >> 7;
    int k = i & 127;
    float v;
    if (n < 384) {
        v = gru_k[k * 384 + n];
    } else if (n < 768) {
        v = gru_rk[k * 384 + (n - 384)];
    } else {
        int j = n - 768;
        v = (j < 128) ? W_msg[k * 128 + j] : W_msg[(128 + k) * 128 + (j - 128)];
    }
    __half hi = __float2half_rn(v);
    float lo = v - __half2float(hi);
    WtHi[i] = hi;
    WtLo[i] = __float2half_rn(lo);
}

// ================= CSR build: group pairs by `second` =================
__global__ void k_hist(const int* __restrict__ second, int* __restrict__ cnt, int P) {
    int p = blockIdx.x * blockDim.x + threadIdx.x;
    if (p < P) atomicAdd(&cnt[second[p] + 1], 1);
}

__global__ void k_scan1(int* __restrict__ data, int* __restrict__ blk, int n) {
    __shared__ int sh[1024];
    int tid = threadIdx.x;
    int i = blockIdx.x * 1024 + tid;
    int v = (i < n) ? data[i] : 0;
    sh[tid] = v;
    __syncthreads();
    #pragma unroll
    for (int off = 1; off < 1024; off <<= 1) {
        int t = (tid >= off) ? sh[tid - off] : 0;
        __syncthreads();
        sh[tid] += t;
        __syncthreads();
    }
    if (i < n) data[i] = sh[tid];
    if (tid == 1023) blk[blockIdx.x] = sh[1023];
}

__global__ void k_scan2(int* __restrict__ blk, int nb) {
    __shared__ int sh[1024];
    int tid = threadIdx.x;
    int v = (tid < nb) ? blk[tid] : 0;
    sh[tid] = v;
    __syncthreads();
    #pragma unroll
    for (int off = 1; off < 1024; off <<= 1) {
        int t = (tid >= off) ? sh[tid - off] : 0;
        __syncthreads();
        sh[tid] += t;
        __syncthreads();
    }
    if (tid < nb) blk[tid] = sh[tid] - v;   // exclusive
}

__global__ void k_scan3(int* __restrict__ data, const int* __restrict__ blk,
                        int* __restrict__ cur, int n, int E) {
    int i = blockIdx.x * 1024 + threadIdx.x;
    if (i >= n) return;
    int v = data[i] + blk[blockIdx.x];
    data[i] = v;
    if (i < E) cur[i] = v;
}

__global__ void k_scatter(const int* __restrict__ first, const int* __restrict__ second,
                          int* __restrict__ cur, int* __restrict__ pfirst, int P) {
    int p = blockIdx.x * blockDim.x + threadIdx.x;
    if (p >= P) return;
    int s = second[p];
    int idx = atomicAdd(&cur[s], 1);
    pfirst[idx] = first[p];
}

// ================= Segment message sum: agg[s] = sum_i selu(U[pf[i]] + Vb[s]) =================
__global__ void seg_msg(const float* __restrict__ UV,
                        const int* __restrict__ off, const int* __restrict__ pfirst,
                        float* __restrict__ agg, int E)
{
    int s = blockIdx.x * 8 + (threadIdx.x >> 5);
    if (s >= E) return;
    int lane = threadIdx.x & 31;
    int beg = off[s], end = off[s + 1];
    float4 vb = *(const float4*)(UV + (size_t)s * 256 + 128 + lane * 4);
    float4 acc = make_float4(0.f, 0.f, 0.f, 0.f);
    int i = beg;
    for (; i + 4 <= end; i += 4) {
        int f0 = pfirst[i];
        int f1 = pfirst[i + 1];
        int f2 = pfirst[i + 2];
        int f3 = pfirst[i + 3];
        float4 u0 = *(const float4*)(UV + (size_t)f0 * 256 + lane * 4);
        float4 u1 = *(const float4*)(UV + (size_t)f1 * 256 + lane * 4);
        float4 u2 = *(const float4*)(UV + (size_t)f2 * 256 + lane * 4);
        float4 u3 = *(const float4*)(UV + (size_t)f3 * 256 + lane * 4);
        acc.x += selu_f(u0.x + vb.x) + selu_f(u1.x + vb.x) + selu_f(u2.x + vb.x) + selu_f(u3.x + vb.x);
        acc.y += selu_f(u0.y + vb.y) + selu_f(u1.y + vb.y) + selu_f(u2.y + vb.y) + selu_f(u3.y + vb.y);
        acc.z += selu_f(u0.z + vb.z) + selu_f(u1.z + vb.z) + selu_f(u2.z + vb.z) + selu_f(u3.z + vb.z);
        acc.w += selu_f(u0.w + vb.w) + selu_f(u1.w + vb.w) + selu_f(u2.w + vb.w) + selu_f(u3.w + vb.w);
    }
    for (; i < end; i++) {
        int f = pfirst[i];
        float4 u = *(const float4*)(UV + (size_t)f * 256 + lane * 4);
        acc.x += selu_f(u.x + vb.x);
        acc.y += selu_f(u.y + vb.y);
        acc.z += selu_f(u.z + vb.z);
        acc.w += selu_f(u.w + vb.w);
    }
    *(float4*)(agg + (size_t)s * 128 + lane * 4) = acc;
}

// ================= Tensor-core GEMM: 96x128 tile, 2 CTAs/SM, fused loads + unchained MMAs =================
#define SA_HI 0
#define SA_LO 24576
#define SB_HI 49152
#define SB_LO 81920
#define SMEM_SZ 114688

template<bool HAS_BIAS>
__global__ void __launch_bounds__(256, 2) mma_gemm(
    const float* __restrict__ A, const __half* __restrict__ BtHi,
    const __half* __restrict__ BtLo, const float* __restrict__ bias,
    float* __restrict__ C, int M, int Ntot)
{
    extern __shared__ __align__(128) char smem[];
    const uint32_t sb = smem_u32(smem);
    const int tid = threadIdx.x;
    const int row0 = blockIdx.x * 96;
    const int col0 = blockIdx.y * 128;

    // ---- B tiles via cp.async (issued first; fly while A is split) ----
    #pragma unroll
    for (int it = 0; it < 16; it++) {
        int idx = it * 256 + tid;
        int m = idx >> 11;
        int ci = idx & 2047;
        int n = ci >> 4;
        int c8 = ci & 15;
        const __half* src = (m ? BtLo : BtHi) + (size_t)(col0 + n) * 128 + c8 * 8;
        uint32_t dst = sb + (m ? SB_LO : SB_HI) + sw_off(n, c8);
        CP_ASYNC16(dst, src);
    }
    CP_COMMIT();

    // ---- A tile: 96 x 128 fp32 -> fp16 hi/lo swizzled ----
    #pragma unroll
    for (int it = 0; it < 12; it++) {
        int idx = it * 256 + tid;
        int r = idx >> 5;
        int c4 = idx & 31;
        int grow = row0 + r;
        float4 v = make_float4(0.f, 0.f, 0.f, 0.f);
        if (grow < M) v = *(const float4*)(A + (size_t)grow * 128 + c4 * 4);
        uint2 hu, lu;
        split4(v, hu, lu);
        uint32_t off = ((uint32_t)r << 8) + (uint32_t)((((c4 >> 1) ^ (r & 7)) << 4) | ((c4 & 1) << 3));
        *(uint2*)(smem + SA_HI + off) = hu;
        *(uint2*)(smem + SA_LO + off) = lu;
    }
    CP_WAIT0();
    __syncthreads();

    const int wid = tid >> 5;
    const int lane = tid & 31;
    const int wr = wid >> 2;       // 0..1 : 48-row groups
    const int wc = wid & 3;        // 0..3 : 32-col groups
    const int g = lane >> 3;
    const int l8 = lane & 7;

    float acc[3][4][4];
    #pragma unroll
    for (int i = 0; i < 3; i++)
        #pragma unroll
        for (int j = 0; j < 4; j++)
            #pragma unroll
            for (int q = 0; q < 4; q++) acc[i][j][q] = 0.f;

    uint32_t aBase[3], aX[3];
    #pragma unroll
    for (int mt = 0; mt < 3; mt++) {
        int r = wr * 48 + mt * 16 + (g & 1) * 8 + l8;
        aBase[mt] = (uint32_t)r << 8;
        aX[mt] = (uint32_t)(r & 7);
    }
    uint32_t bBase[2], bX[2];
    #pragma unroll
    for (int nt = 0; nt < 2; nt++) {
        int r = wc * 32 + nt * 16 + (g >> 1) * 8 + l8;
        bBase[nt] = (uint32_t)r << 8;
        bX[nt] = (uint32_t)(r & 7);
    }
    const uint32_t aC8 = (uint32_t)(g >> 1);
    const uint32_t bC8 = (uint32_t)(g & 1);

    // fused k-loop: load all fragments once, then issue the 3 products in
    // SEPARATE sweeps so no accumulator sees back-to-back dependent MMAs.
    #pragma unroll
    for (int ks = 0; ks < 8; ks++) {
        uint32_t aHi[3][4], aLo[3][4];
        #pragma unroll
        for (int mt = 0; mt < 3; mt++) {
            uint32_t aoff = aBase[mt] + ((((uint32_t)(2 * ks) + aC8) ^ aX[mt]) << 4);
            ldsm_x4(sb + SA_HI + aoff, aHi[mt]);
            ldsm_x4(sb + SA_LO + aoff, aLo[mt]);
        }
        uint32_t bHi[2][4], bLo[2][4];
        #pragma unroll
        for (int nt = 0; nt < 2; nt++) {
            uint32_t boff = bBase[nt] + ((((uint32_t)(2 * ks) + bC8) ^ bX[nt]) << 4);
            ldsm_x4(sb + SB_HI + boff, bHi[nt]);
            ldsm_x4(sb + SB_LO + boff, bLo[nt]);
        }
        // sweep 1: Ahi * Bhi (12 independent MMAs)
        #pragma unroll
        for (int mt = 0; mt < 3; mt++)
            #pragma unroll
            for (int j = 0; j < 4; j++) {
                uint32_t b0 = (j & 1) ? bHi[j >> 1][2] : bHi[j >> 1][0];
                uint32_t b1 = (j & 1) ? bHi[j >> 1][3] : bHi[j >> 1][1];
                mma16816(acc[mt][j], aHi[mt], b0, b1);
            }
        // sweep 2: Ahi * Blo
        #pragma unroll
        for (int mt = 0; mt < 3; mt++)
            #pragma unroll
            for (int j = 0; j < 4; j++) {
                uint32_t b0 = (j & 1) ? bLo[j >> 1][2] : bLo[j >> 1][0];
                uint32_t b1 = (j & 1) ? bLo[j >> 1][3] : bLo[j >> 1][1];
                mma16816(acc[mt][j], aHi[mt], b0, b1);
            }
        // sweep 3: Alo * Bhi
        #pragma unroll
        for (int mt = 0; mt < 3; mt++)
            #pragma unroll
            for (int j = 0; j < 4; j++) {
                uint32_t b0 = (j & 1) ? bHi[j >> 1][2] : bHi[j >> 1][0];
                uint32_t b1 = (j & 1) ? bHi[j >> 1][3] : bHi[j >> 1][1];
                mma16816(acc[mt][j], aLo[mt], b0, b1);
            }
    }

    // ---- epilogue ----
    #pragma unroll
    for (int mt = 0; mt < 3; mt++) {
        int r0a = row0 + wr * 48 + mt * 16 + (lane >> 2);
        #pragma unroll
        for (int j = 0; j < 4; j++) {
            int c = col0 + wc * 32 + j * 8 + (lane & 3) * 2;
            float b0 = 0.f, b1 = 0.f;
            if (HAS_BIAS) { b0 = bias[c]; b1 = bias[c + 1]; }
            if (r0a < M) {
                float2 v; v.x = acc[mt][j][0] + b0; v.y = acc[mt][j][1] + b1;
                *(float2*)(C + (size_t)r0a * Ntot + c) = v;
            }
            if (r0a + 8 < M) {
                float2 v; v.x = acc[mt][j][2] + b0; v.y = acc[mt][j][3] + b1;
                *(float2*)(C + (size_t)(r0a + 8) * Ntot + c) = v;
            }
        }
    }
}

// ---------------- FFMA SGEMM (small readout GEMMs) ----------------
#define APAD 4
template<bool HAS_BIAS, bool ACT_SELU>
__global__ void __launch_bounds__(256) sgemm_kernel(
    const float* __restrict__ A, const float* __restrict__ B,
    const float* __restrict__ bias, float* __restrict__ C,
    int M, int N, int K)
{
    __shared__ float As[16][128 + APAD];
    __shared__ float Bs[16][128];

    const int row0 = blockIdx.x * 128;
    const int col0 = blockIdx.y * 128;
    const int tid = threadIdx.x;
    const int tm = tid >> 4;
    const int tn = tid & 15;

    float acc[8][8];
    #pragma unroll
    for (int i = 0; i < 8; i++)
        #pragma unroll
        for (int j = 0; j < 8; j++) acc[i][j] = 0.f;

    for (int k0 = 0; k0 < K; k0 += 16) {
        #pragma unroll
        for (int it = 0; it < 2; it++) {
            int fi = tid + it * 256;
            int r = fi >> 2;
            int kq = fi & 3;
            int grow = row0 + r;
            float4 v = make_float4(0.f, 0.f, 0.f, 0.f);
            if (grow < M)
                v = *(const float4*)(A + (size_t)grow * K + k0 + kq * 4);
            As[kq * 4 + 0][r] = v.x;
            As[kq * 4 + 1][r] = v.y;
            As[kq * 4 + 2][r] = v.z;
            As[kq * 4 + 3][r] = v.w;
        }
        #pragma unroll
        for (int it = 0; it < 2; it++) {
            int fi = tid + it * 256;
            int kr = fi >> 5;
            int cq = fi & 31;
            float4 v = *(const float4*)(B + (size_t)(k0 + kr) * N + col0 + cq * 4);
            *(float4*)(&Bs[kr][cq * 4]) = v;
        }
        __syncthreads();
        #pragma unroll
        for (int k = 0; k < 16; k++) {
            float a[8], b[8];
            *(float4*)(a)     = *(const float4*)(&As[k][tm * 8]);
            *(float4*)(a + 4) = *(const float4*)(&As[k][tm * 8 + 4]);
            *(float4*)(b)     = *(const float4*)(&Bs[k][tn * 8]);
            *(float4*)(b + 4) = *(const float4*)(&Bs[k][tn * 8 + 4]);
            #pragma unroll
            for (int i = 0; i < 8; i++)
                #pragma unroll
                for (int j = 0; j < 8; j++)
                    acc[i][j] = fmaf(a[i], b[j], acc[i][j]);
        }
        __syncthreads();
    }

    float bcol[8];
    if (HAS_BIAS) {
        #pragma unroll
        for (int j = 0; j < 8; j++) bcol[j] = bias[col0 + tn * 8 + j];
    }
    #pragma unroll
    for (int i = 0; i < 8; i++) {
        int r = row0 + tm * 8 + i;
        if (r >= M) continue;
        #pragma unroll
        for (int j = 0; j < 8; j += 4) {
            float4 v;
            float t0 = acc[i][j + 0], t1 = acc[i][j + 1], t2 = acc[i][j + 2], t3 = acc[i][j + 3];
            if (HAS_BIAS) { t0 += bcol[j]; t1 += bcol[j + 1]; t2 += bcol[j + 2]; t3 += bcol[j + 3]; }
            if (ACT_SELU) { t0 = selu_f(t0); t1 = selu_f(t1); t2 = selu_f(t2); t3 = selu_f(t3); }
            v.x = t0; v.y = t1; v.z = t2; v.w = t3;
            *(float4*)(C + (size_t)r * N + col0 + tn * 8 + j) = v;
        }
    }
}

// ---------------- GRU gates ----------------
__global__ void gates_kernel(const float* __restrict__ X1, const float* __restrict__ X2,
                             float* __restrict__ h, int E)
{
    int i = blockIdx.x * blockDim.x + threadIdx.x;
    if (i >= E * 32) return;
    int e = i >> 5;
    int q = i & 31;
    size_t b384 = (size_t)e * 384 + q * 4;
    size_t b128 = (size_t)e * 128 + q * 4;
    float4 x1z = *(const float4*)(X1 + b384);
    float4 x1r = *(const float4*)(X1 + b384 + 128);
    float4 x1h = *(const float4*)(X1 + b384 + 256);
    float4 x2z = *(const float4*)(X2 + b384);
    float4 x2r = *(const float4*)(X2 + b384 + 128);
    float4 x2h = *(const float4*)(X2 + b384 + 256);
    float4 hv  = *(const float4*)(h + b128);
    float4 o;
    { float z = sigmoid_f(x1z.x + x2z.x); float r = sigmoid_f(x1r.x + x2r.x);
      float hh = tanhf(x1h.x + r * x2h.x); o.x = z * hv.x + (1.f - z) * hh; }
    { float z = sigmoid_f(x1z.y + x2z.y); float r = sigmoid_f(x1r.y + x2r.y);
      float hh = tanhf(x1h.y + r * x2h.y); o.y = z * hv.y + (1.f - z) * hh; }
    { float z = sigmoid_f(x1z.z + x2z.z); float r = sigmoid_f(x1r.z + x2r.z);
      float hh = tanhf(x1h.z + r * x2h.z); o.z = z * hv.z + (1.f - z) * hh; }
    { float z = sigmoid_f(x1z.w + x2z.w); float r = sigmoid_f(x1r.w + x2r.w);
      float hh = tanhf(x1h.w + r * x2h.w); o.w = z * hv.w + (1.f - z) * hh; }
    *(float4*)(h + b128) = o;
}

// ---------------- Graph pooling ----------------
__global__ void pool_kernel(const float* __restrict__ h, const int* __restrict__ gids,
                            float* __restrict__ pool, int E)
{
    int i = blockIdx.x * blockDim.x + threadIdx.x;
    if (i >= E * 32) return;
    int e = i >> 5;
    int q = i & 31;
    int g = gids[e];
    float4 v = *(const float4*)(h + (size_t)e * 128 + q * 4);
    float* dst = pool + (size_t)g * 128 + q * 4;
    asm volatile("red.global.add.v4.f32 [%0], {%1,%2,%3,%4};"
                 :: "l"(dst), "f"(v.x), "f"(v.y), "f"(v.z), "f"(v.w) : "memory");
}

// ---------------- Final readout ----------------
__global__ void final_kernel(const float* __restrict__ h2, const float* __restrict__ W3,
                             const float* __restrict__ b3, float* __restrict__ out, int G)
{
    int w = (blockIdx.x * blockDim.x + threadIdx.x) >> 5;
    int lane = threadIdx.x & 31;
    if (w >= G) return;
    float s = 0.f;
    #pragma unroll
    for (int k = 0; k < 8; k++) {
        int j = k * 32 + lane;
        s = fmaf(h2[(size_t)w * 256 + j], W3[j], s);
    }
    #pragma unroll
    for (int off = 16; off > 0; off >>= 1)
        s += __shfl_xor_sync(0xffffffffu, s, off);
    if (lane == 0) out[w] = s + b3[0];
}

// ---------------- Host orchestration ----------------
extern "C" void kernel_launch(void* const* d_in, const int* in_sizes, int n_in,
                              void* d_out, int out_size)
{
    int o = (n_in >= 16) ? 0 : -1;

    const float* link_state = (const float*)d_in[0];
    const int*   gids       = (const int*)d_in[1];
    const int*   first      = (const int*)d_in[2];
    const int*   second     = (const int*)d_in[3];
    const float* W_msg      = (const float*)d_in[5 + o];
    const float* b_msg      = (const float*)d_in[6 + o];
    const float* gru_k      = (const float*)d_in[7 + o];
    const float* gru_rk     = (const float*)d_in[8 + o];
    const float* gru_b      = (const float*)d_in[9 + o];
    const float* W1         = (const float*)d_in[10 + o];
    const float* b1         = (const float*)d_in[11 + o];
    const float* W2         = (const float*)d_in[12 + o];
    const float* b2         = (const float*)d_in[13 + o];
    const float* W3         = (const float*)d_in[14 + o];
    const float* b3         = (const float*)d_in[15 + o];

    const int E = in_sizes[1];
    const int P = in_sizes[2];
    const int G = out_size;

    float *h, *agg, *UV, *X1, *X2, *pool, *r1, *r2, *b256;
    __half *WtHi, *WtLo;
    int *off, *cur, *pfirst, *blk;
    cudaGetSymbolAddress((void**)&h,    d_h);
    cudaGetSymbolAddress((void**)&agg,  d_agg);
    cudaGetSymbolAddress((void**)&UV,   d_UV);
    cudaGetSymbolAddress((void**)&X1,   d_X1);
    cudaGetSymbolAddress((void**)&X2,   d_X2);
    cudaGetSymbolAddress((void**)&pool, d_pool);
    cudaGetSymbolAddress((void**)&r1,   d_r1);
    cudaGetSymbolAddress((void**)&r2,   d_r2);
    cudaGetSymbolAddress((void**)&b256, d_b256);
    cudaGetSymbolAddress((void**)&WtHi, d_WtHi);
    cudaGetSymbolAddress((void**)&WtLo, d_WtLo);
    cudaGetSymbolAddress((void**)&off,    d_off);
    cudaGetSymbolAddress((void**)&cur,    d_cur);
    cudaGetSymbolAddress((void**)&pfirst, d_pfirst);
    cudaGetSymbolAddress((void**)&blk,    d_blk);

    cudaFuncSetAttribute(mma_gemm<true>,  cudaFuncAttributeMaxDynamicSharedMemorySize, SMEM_SZ);
    cudaFuncSetAttribute(mma_gemm<false>, cudaFuncAttributeMaxDynamicSharedMemorySize, SMEM_SZ);

    // side stream + events for fork/join overlap (created once, pre-capture)
    static cudaStream_t s1 = nullptr;
    static cudaEvent_t ev_h = nullptr, ev_x2 = nullptr;
    if (s1 == nullptr) {
        cudaStreamCreateWithFlags(&s1, cudaStreamNonBlocking);
        cudaEventCreateWithFlags(&ev_h,  cudaEventDisableTiming);
        cudaEventCreateWithFlags(&ev_x2, cudaEventDisableTiming);
    }

    const __half* WkHi  = WtHi;              const __half* WkLo  = WtLo;
    const __half* WrkHi = WtHi + 384 * 128;  const __half* WrkLo = WtLo + 384 * 128;
    const __half* WuvHi = WtHi + 768 * 128;  const __half* WuvLo = WtLo + 768 * 128;

    const int mb = (E + 95) / 96;
    const int nscan = E + 1;
    const int nblks = (nscan + 1023) / 1024;

    // ---- one-time prep ----
    prep_weights<<<(1024 * 128 + 255) / 256, 256>>>(gru_k, gru_rk, W_msg, b_msg, WtHi, WtLo, b256);
    cudaMemcpyAsync(h, link_state, (size_t)E * DIM * sizeof(float), cudaMemcpyDeviceToDevice);
    cudaMemsetAsync(off, 0, (size_t)nscan * sizeof(int));
    k_hist<<<(P + 255) / 256, 256>>>(second, off, P);
    k_scan1<<<nblks, 1024>>>(off, blk, nscan);
    k_scan2<<<1, 1024>>>(blk, nblks);
    k_scan3<<<nblks, 1024>>>(off, blk, cur, nscan, E);
    k_scatter<<<(P + 255) / 256, 256>>>(first, second, cur, pfirst, P);

    for (int t = 0; t < TSTEPS; t++) {
        // h is ready on stream 0
        cudaEventRecord(ev_h, 0);
        // fork: X2 = h @ rec_kernel + gru_bias[1] on side stream
        cudaStreamWaitEvent(s1, ev_h, 0);
        mma_gemm<true><<<dim3(mb, 3), 256, SMEM_SZ, s1>>>(h, WrkHi, WrkLo, gru_b + 384, X2, E, 384);
        cudaEventRecord(ev_x2, s1);
        // main stream: UV (V gets +b_msg) -> seg_msg -> X1
        mma_gemm<true><<<dim3(mb, 2), 256, SMEM_SZ>>>(h, WuvHi, WuvLo, b256, UV, E, 256);
        seg_msg<<<(E + 7) / 8, 256>>>(UV, off, pfirst, agg, E);
        mma_gemm<true><<<dim3(mb, 3), 256, SMEM_SZ>>>(agg, WkHi, WkLo, gru_b, X1, E, 384);
        // join: gates needs X1 (stream 0) and X2 (s1)
        cudaStreamWaitEvent(0, ev_x2, 0);
        gates_kernel<<<(E * 32 + 255) / 256, 256>>>(X1, X2, h, E);
    }

    cudaMemsetAsync(pool, 0, (size_t)G * DIM * sizeof(float));
    pool_kernel<<<(E * 32 + 255) / 256, 256>>>(h, gids, pool, E);
    const int gblocks = (G + 127) / 128;
    sgemm_kernel<true, true><<<dim3(gblocks, 2), 256>>>(pool, W1, b1, r1, G, 256, 128);
    sgemm_kernel<true, true><<<dim3(gblocks, 2), 256>>>(r1, W2, b2, r2, G, 256, 256);
    final_kernel<<<(G * 32 + 255) / 256, 256>>>(r2, W3, b3, (float*)d_out, G);
}

// round 15
// speedup vs baseline: 1.0052x; 1.0052x over previous
#include <cuda_runtime.h>
#include <cuda_fp16.h>
#include <math.h>
#include <stdint.h>

// ---------------- Problem constants ----------------
#define DIM   128
#define E_MAX 100000
#define P_MAX 800000
#define G_MAX 1000
#define TSTEPS 8

// ---------------- Device scratch (no allocations allowed) ----------------
__device__ float d_h  [E_MAX * DIM];
__device__ float d_agg[E_MAX * DIM];
__device__ float d_UV [E_MAX * 256];
__device__ float d_X1 [E_MAX * 384];
__device__ float d_X2 [E_MAX * 384];
__device__ float d_pool[G_MAX * DIM];
__device__ float d_r1 [G_MAX * 256];
__device__ float d_r2 [G_MAX * 256];
__device__ float d_b256[256];          // [0..127]=0, [128..255]=b_msg
// split+transposed weights: rows 0..383 = gru_kernel^T, 384..767 = gru_rec^T, 768..1023 = Wuv^T
__device__ __half d_WtHi[1024 * 128];
__device__ __half d_WtLo[1024 * 128];
// CSR grouping of pairs by `second`
__device__ int d_off   [E_MAX + 1];
__device__ int d_cur   [E_MAX];
__device__ int d_pfirst[P_MAX];
__device__ int d_blk   [256];

// ---------------- math helpers ----------------
__device__ __forceinline__ float selu_f(float x) {
    const float sc = 1.0507009873554805f;
    const float al = 1.6732632423543772f;
    return x > 0.f ? sc * x : sc * al * (expf(x) - 1.f);
}
__device__ __forceinline__ float sigmoid_f(float x) { return 1.f / (1.f + expf(-x)); }

__device__ __forceinline__ uint32_t smem_u32(const void* p) {
    uint32_t a;
    asm("{ .reg .u64 t; cvta.to.shared.u64 t, %1; cvt.u32.u64 %0, t; }" : "=r"(a) : "l"(p));
    return a;
}

#define CP_ASYNC16(dst, src) \
    asm volatile("cp.async.cg.shared.global [%0], [%1], 16;" :: "r"(dst), "l"(src))
#define CP_COMMIT() asm volatile("cp.async.commit_group;" ::: "memory")
#define CP_WAIT0()  asm volatile("cp.async.wait_group 0;" ::: "memory")

// swizzled byte offset of 16B chunk c8 (0..15) in row r (256B rows)
__device__ __forceinline__ uint32_t sw_off(int r, int c8) {
    return ((uint32_t)r << 8) + (uint32_t)((c8 ^ (r & 7)) << 4);
}

__device__ __forceinline__ void ldsm_x4(uint32_t addr, uint32_t* r) {
    asm volatile("ldmatrix.sync.aligned.m8n8.x4.shared.b16 {%0,%1,%2,%3}, [%4];"
                 : "=r"(r[0]), "=r"(r[1]), "=r"(r[2]), "=r"(r[3]) : "r"(addr));
}

__device__ __forceinline__ void mma16816(float* c, const uint32_t* a, uint32_t b0, uint32_t b1) {
    asm volatile(
        "mma.sync.aligned.m16n8k16.row.col.f32.f16.f16.f32 "
        "{%0,%1,%2,%3}, {%4,%5,%6,%7}, {%8,%9}, {%0,%1,%2,%3};"
        : "+f"(c[0]), "+f"(c[1]), "+f"(c[2]), "+f"(c[3])
        : "r"(a[0]), "r"(a[1]), "r"(a[2]), "r"(a[3]), "r"(b0), "r"(b1));
}

// split fp32 float4 into fp16 hi/lo pairs packed as uint2
__device__ __forceinline__ void split4(float4 v, uint2& hu, uint2& lu) {
    __half2 h01 = __floats2half2_rn(v.x, v.y);
    __half2 h23 = __floats2half2_rn(v.z, v.w);
    float lx = v.x - __half2float(__low2half(h01));
    float ly = v.y - __half2float(__high2half(h01));
    float lz = v.z - __half2float(__low2half(h23));
    float lw = v.w - __half2float(__high2half(h23));
    __half2 l01 = __floats2half2_rn(lx, ly);
    __half2 l23 = __floats2half2_rn(lz, lw);
    hu.x = *(uint32_t*)&h01; hu.y = *(uint32_t*)&h23;
    lu.x = *(uint32_t*)&l01; lu.y = *(uint32_t*)&l23;
}

// ---------------- Weight prep ----------------
__global__ void prep_weights(const float* __restrict__ gru_k, const float* __restrict__ gru_rk,
                             const float* __restrict__ W_msg, const float* __restrict__ b_msg,
                             __half* __restrict__ WtHi, __half* __restrict__ WtLo,
                             float* __restrict__ b256)
{
    int i = blockIdx.x * blockDim.x + threadIdx.x;
    if (i >= 1024 * 128) return;
    if (i < 256) b256[i] = (i < 128) ? 0.f : b_msg[i - 128];
    int n = i >> 7;
    int k = i & 127;
    float v;
    if (n < 384) {
        v = gru_k[k * 384 + n];
    } else if (n < 768) {
        v = gru_rk[k * 384 + (n - 384)];
    } else {
        int j = n - 768;
        v = (j < 128) ? W_msg[k * 128 + j] : W_msg[(128 + k) * 128 + (j - 128)];
    }
    __half hi = __float2half_rn(v);
    float lo = v - __half2float(hi);
    WtHi[i] = hi;
    WtLo[i] = __float2half_rn(lo);
}

// ================= CSR build: group pairs by `second` =================
__global__ void k_hist(const int* __restrict__ second, int* __restrict__ cnt, int P) {
    int p = blockIdx.x * blockDim.x + threadIdx.x;
    if (p < P) atomicAdd(&cnt[second[p] + 1], 1);
}

__global__ void k_scan1(int* __restrict__ data, int* __restrict__ blk, int n) {
    __shared__ int sh[1024];
    int tid = threadIdx.x;
    int i = blockIdx.x * 1024 + tid;
    int v = (i < n) ? data[i] : 0;
    sh[tid] = v;
    __syncthreads();
    #pragma unroll
    for (int off = 1; off < 1024; off <<= 1) {
        int t = (tid >= off) ? sh[tid - off] : 0;
        __syncthreads();
        sh[tid] += t;
        __syncthreads();
    }
    if (i < n) data[i] = sh[tid];
    if (tid == 1023) blk[blockIdx.x] = sh[1023];
}

__global__ void k_scan2(int* __restrict__ blk, int nb) {
    __shared__ int sh[1024];
    int tid = threadIdx.x;
    int v = (tid < nb) ? blk[tid] : 0;
    sh[tid] = v;
    __syncthreads();
    #pragma unroll
    for (int off = 1; off < 1024; off <<= 1) {
        int t = (tid >= off) ? sh[tid - off] : 0;
        __syncthreads();
        sh[tid] += t;
        __syncthreads();
    }
    if (tid < nb) blk[tid] = sh[tid] - v;   // exclusive
}

__global__ void k_scan3(int* __restrict__ data, const int* __restrict__ blk,
                        int* __restrict__ cur, int n, int E) {
    int i = blockIdx.x * 1024 + threadIdx.x;
    if (i >= n) return;
    int v = data[i] + blk[blockIdx.x];
    data[i] = v;
    if (i < E) cur[i] = v;
}

__global__ void k_scatter(const int* __restrict__ first, const int* __restrict__ second,
                          int* __restrict__ cur, int* __restrict__ pfirst, int P) {
    int p = blockIdx.x * blockDim.x + threadIdx.x;
    if (p >= P) return;
    int s = second[p];
    int idx = atomicAdd(&cur[s], 1);
    pfirst[idx] = first[p];
}

// ================= Segment message sum over s in [sBeg, sEnd) =================
__global__ void seg_msg(const float* __restrict__ UV,
                        const int* __restrict__ off, const int* __restrict__ pfirst,
                        float* __restrict__ agg, int sBeg, int sEnd)
{
    int s = sBeg + blockIdx.x * 8 + (threadIdx.x >> 5);
    if (s >= sEnd) return;
    int lane = threadIdx.x & 31;
    int beg = off[s], end = off[s + 1];
    float4 vb = *(const float4*)(UV + (size_t)s * 256 + 128 + lane * 4);
    float4 acc = make_float4(0.f, 0.f, 0.f, 0.f);
    int i = beg;
    for (; i + 4 <= end; i += 4) {
        int f0 = pfirst[i];
        int f1 = pfirst[i + 1];
        int f2 = pfirst[i + 2];
        int f3 = pfirst[i + 3];
        float4 u0 = *(const float4*)(UV + (size_t)f0 * 256 + lane * 4);
        float4 u1 = *(const float4*)(UV + (size_t)f1 * 256 + lane * 4);
        float4 u2 = *(const float4*)(UV + (size_t)f2 * 256 + lane * 4);
        float4 u3 = *(const float4*)(UV + (size_t)f3 * 256 + lane * 4);
        acc.x += selu_f(u0.x + vb.x) + selu_f(u1.x + vb.x) + selu_f(u2.x + vb.x) + selu_f(u3.x + vb.x);
        acc.y += selu_f(u0.y + vb.y) + selu_f(u1.y + vb.y) + selu_f(u2.y + vb.y) + selu_f(u3.y + vb.y);
        acc.z += selu_f(u0.z + vb.z) + selu_f(u1.z + vb.z) + selu_f(u2.z + vb.z) + selu_f(u3.z + vb.z);
        acc.w += selu_f(u0.w + vb.w) + selu_f(u1.w + vb.w) + selu_f(u2.w + vb.w) + selu_f(u3.w + vb.w);
    }
    for (; i < end; i++) {
        int f = pfirst[i];
        float4 u = *(const float4*)(UV + (size_t)f * 256 + lane * 4);
        acc.x += selu_f(u.x + vb.x);
        acc.y += selu_f(u.y + vb.y);
        acc.z += selu_f(u.z + vb.z);
        acc.w += selu_f(u.w + vb.w);
    }
    *(float4*)(agg + (size_t)s * 128 + lane * 4) = acc;
}

// ================= Tensor-core GEMM: 96x128 tile, 2 CTAs/SM, fused loads =================
#define SA_HI 0
#define SA_LO 24576
#define SB_HI 49152
#define SB_LO 81920
#define SMEM_SZ 114688

template<bool HAS_BIAS>
__global__ void __launch_bounds__(256, 2) mma_gemm(
    const float* __restrict__ A, const __half* __restrict__ BtHi,
    const __half* __restrict__ BtLo, const float* __restrict__ bias,
    float* __restrict__ C, int M, int Ntot)
{
    extern __shared__ __align__(128) char smem[];
    const uint32_t sb = smem_u32(smem);
    const int tid = threadIdx.x;
    const int row0 = blockIdx.x * 96;
    const int col0 = blockIdx.y * 128;

    // ---- B tiles via cp.async (issued first; fly while A is split) ----
    #pragma unroll
    for (int it = 0; it < 16; it++) {
        int idx = it * 256 + tid;
        int m = idx >> 11;
        int ci = idx & 2047;
        int n = ci >> 4;
        int c8 = ci & 15;
        const __half* src = (m ? BtLo : BtHi) + (size_t)(col0 + n) * 128 + c8 * 8;
        uint32_t dst = sb + (m ? SB_LO : SB_HI) + sw_off(n, c8);
        CP_ASYNC16(dst, src);
    }
    CP_COMMIT();

    // ---- A tile: 96 x 128 fp32 -> fp16 hi/lo swizzled ----
    #pragma unroll
    for (int it = 0; it < 12; it++) {
        int idx = it * 256 + tid;
        int r = idx >> 5;
        int c4 = idx & 31;
        int grow = row0 + r;
        float4 v = make_float4(0.f, 0.f, 0.f, 0.f);
        if (grow < M) v = *(const float4*)(A + (size_t)grow * 128 + c4 * 4);
        uint2 hu, lu;
        split4(v, hu, lu);
        uint32_t off = ((uint32_t)r << 8) + (uint32_t)((((c4 >> 1) ^ (r & 7)) << 4) | ((c4 & 1) << 3));
        *(uint2*)(smem + SA_HI + off) = hu;
        *(uint2*)(smem + SA_LO + off) = lu;
    }
    CP_WAIT0();
    __syncthreads();

    const int wid = tid >> 5;
    const int lane = tid & 31;
    const int wr = wid >> 2;       // 0..1 : 48-row groups
    const int wc = wid & 3;        // 0..3 : 32-col groups
    const int g = lane >> 3;
    const int l8 = lane & 7;

    float acc[3][4][4];
    #pragma unroll
    for (int i = 0; i < 3; i++)
        #pragma unroll
        for (int j = 0; j < 4; j++)
            #pragma unroll
            for (int q = 0; q < 4; q++) acc[i][j][q] = 0.f;

    uint32_t aBase[3], aX[3];
    #pragma unroll
    for (int mt = 0; mt < 3; mt++) {
        int r = wr * 48 + mt * 16 + (g & 1) * 8 + l8;
        aBase[mt] = (uint32_t)r << 8;
        aX[mt] = (uint32_t)(r & 7);
    }
    uint32_t bBase[2], bX[2];
    #pragma unroll
    for (int nt = 0; nt < 2; nt++) {
        int r = wc * 32 + nt * 16 + (g >> 1) * 8 + l8;
        bBase[nt] = (uint32_t)r << 8;
        bX[nt] = (uint32_t)(r & 7);
    }
    const uint32_t aC8 = (uint32_t)(g >> 1);
    const uint32_t bC8 = (uint32_t)(g & 1);

    #pragma unroll
    for (int ks = 0; ks < 8; ks++) {
        uint32_t aHi[3][4], aLo[3][4];
        #pragma unroll
        for (int mt = 0; mt < 3; mt++) {
            uint32_t aoff = aBase[mt] + ((((uint32_t)(2 * ks) + aC8) ^ aX[mt]) << 4);
            ldsm_x4(sb + SA_HI + aoff, aHi[mt]);
            ldsm_x4(sb + SA_LO + aoff, aLo[mt]);
        }
        uint32_t bHi[2][4], bLo[2][4];
        #pragma unroll
        for (int nt = 0; nt < 2; nt++) {
            uint32_t boff = bBase[nt] + ((((uint32_t)(2 * ks) + bC8) ^ bX[nt]) << 4);
            ldsm_x4(sb + SB_HI + boff, bHi[nt]);
            ldsm_x4(sb + SB_LO + boff, bLo[nt]);
        }
        #pragma unroll
        for (int mt = 0; mt < 3; mt++)
            #pragma unroll
            for (int j = 0; j < 4; j++) {
                uint32_t b0 = (j & 1) ? bHi[j >> 1][2] : bHi[j >> 1][0];
                uint32_t b1 = (j & 1) ? bHi[j >> 1][3] : bHi[j >> 1][1];
                mma16816(acc[mt][j], aHi[mt], b0, b1);
            }
        #pragma unroll
        for (int mt = 0; mt < 3; mt++)
            #pragma unroll
            for (int j = 0; j < 4; j++) {
                uint32_t b0 = (j & 1) ? bLo[j >> 1][2] : bLo[j >> 1][0];
                uint32_t b1 = (j & 1) ? bLo[j >> 1][3] : bLo[j >> 1][1];
                mma16816(acc[mt][j], aHi[mt], b0, b1);
            }
        #pragma unroll
        for (int mt = 0; mt < 3; mt++)
            #pragma unroll
            for (int j = 0; j < 4; j++) {
                uint32_t b0 = (j & 1) ? bHi[j >> 1][2] : bHi[j >> 1][0];
                uint32_t b1 = (j & 1) ? bHi[j >> 1][3] : bHi[j >> 1][1];
                mma16816(acc[mt][j], aLo[mt], b0, b1);
            }
    }

    // ---- epilogue ----
    #pragma unroll
    for (int mt = 0; mt < 3; mt++) {
        int r0a = row0 + wr * 48 + mt * 16 + (lane >> 2);
        #pragma unroll
        for (int j = 0; j < 4; j++) {
            int c = col0 + wc * 32 + j * 8 + (lane & 3) * 2;
            float b0 = 0.f, b1 = 0.f;
            if (HAS_BIAS) { b0 = bias[c]; b1 = bias[c + 1]; }
            if (r0a < M) {
                float2 v; v.x = acc[mt][j][0] + b0; v.y = acc[mt][j][1] + b1;
                *(float2*)(C + (size_t)r0a * Ntot + c) = v;
            }
            if (r0a + 8 < M) {
                float2 v; v.x = acc[mt][j][2] + b0; v.y = acc[mt][j][3] + b1;
                *(float2*)(C + (size_t)(r0a + 8) * Ntot + c) = v;
            }
        }
    }
}

// ---------------- FFMA SGEMM (small readout GEMMs) ----------------
#define APAD 4
template<bool HAS_BIAS, bool ACT_SELU>
__global__ void __launch_bounds__(256) sgemm_kernel(
    const float* __restrict__ A, const float* __restrict__ B,
    const float* __restrict__ bias, float* __restrict__ C,
    int M, int N, int K)
{
    __shared__ float As[16][128 + APAD];
    __shared__ float Bs[16][128];

    const int row0 = blockIdx.x * 128;
    const int col0 = blockIdx.y * 128;
    const int tid = threadIdx.x;
    const int tm = tid >> 4;
    const int tn = tid & 15;

    float acc[8][8];
    #pragma unroll
    for (int i = 0; i < 8; i++)
        #pragma unroll
        for (int j = 0; j < 8; j++) acc[i][j] = 0.f;

    for (int k0 = 0; k0 < K; k0 += 16) {
        #pragma unroll
        for (int it = 0; it < 2; it++) {
            int fi = tid + it * 256;
            int r = fi >> 2;
            int kq = fi & 3;
            int grow = row0 + r;
            float4 v = make_float4(0.f, 0.f, 0.f, 0.f);
            if (grow < M)
                v = *(const float4*)(A + (size_t)grow * K + k0 + kq * 4);
            As[kq * 4 + 0][r] = v.x;
            As[kq * 4 + 1][r] = v.y;
            As[kq * 4 + 2][r] = v.z;
            As[kq * 4 + 3][r] = v.w;
        }
        #pragma unroll
        for (int it = 0; it < 2; it++) {
            int fi = tid + it * 256;
            int kr = fi >> 5;
            int cq = fi & 31;
            float4 v = *(const float4*)(B + (size_t)(k0 + kr) * N + col0 + cq * 4);
            *(float4*)(&Bs[kr][cq * 4]) = v;
        }
        __syncthreads();
        #pragma unroll
        for (int k = 0; k < 16; k++) {
            float a[8], b[8];
            *(float4*)(a)     = *(const float4*)(&As[k][tm * 8]);
            *(float4*)(a + 4) = *(const float4*)(&As[k][tm * 8 + 4]);
            *(float4*)(b)     = *(const float4*)(&Bs[k][tn * 8]);
            *(float4*)(b + 4) = *(const float4*)(&Bs[k][tn * 8 + 4]);
            #pragma unroll
            for (int i = 0; i < 8; i++)
                #pragma unroll
                for (int j = 0; j < 8; j++)
                    acc[i][j] = fmaf(a[i], b[j], acc[i][j]);
        }
        __syncthreads();
    }

    float bcol[8];
    if (HAS_BIAS) {
        #pragma unroll
        for (int j = 0; j < 8; j++) bcol[j] = bias[col0 + tn * 8 + j];
    }
    #pragma unroll
    for (int i = 0; i < 8; i++) {
        int r = row0 + tm * 8 + i;
        if (r >= M) continue;
        #pragma unroll
        for (int j = 0; j < 8; j += 4) {
            float4 v;
            float t0 = acc[i][j + 0], t1 = acc[i][j + 1], t2 = acc[i][j + 2], t3 = acc[i][j + 3];
            if (HAS_BIAS) { t0 += bcol[j]; t1 += bcol[j + 1]; t2 += bcol[j + 2]; t3 += bcol[j + 3]; }
            if (ACT_SELU) { t0 = selu_f(t0); t1 = selu_f(t1); t2 = selu_f(t2); t3 = selu_f(t3); }
            v.x = t0; v.y = t1; v.z = t2; v.w = t3;
            *(float4*)(C + (size_t)r * N + col0 + tn * 8 + j) = v;
        }
    }
}

// ---------------- GRU gates over rows [eBeg, eEnd) ----------------
__global__ void gates_kernel(const float* __restrict__ X1, const float* __restrict__ X2,
                             float* __restrict__ h, int eBeg, int eEnd)
{
    int i = blockIdx.x * blockDim.x + threadIdx.x;
    int e = eBeg + (i >> 5);
    if (e >= eEnd) return;
    int q = i & 31;
    size_t b384 = (size_t)e * 384 + q * 4;
    size_t b128 = (size_t)e * 128 + q * 4;
    float4 x1z = *(const float4*)(X1 + b384);
    float4 x1r = *(const float4*)(X1 + b384 + 128);
    float4 x1h = *(const float4*)(X1 + b384 + 256);
    float4 x2z = *(const float4*)(X2 + b384);
    float4 x2r = *(const float4*)(X2 + b384 + 128);
    float4 x2h = *(const float4*)(X2 + b384 + 256);
    float4 hv  = *(const float4*)(h + b128);
    float4 o;
    { float z = sigmoid_f(x1z.x + x2z.x); float r = sigmoid_f(x1r.x + x2r.x);
      float hh = tanhf(x1h.x + r * x2h.x); o.x = z * hv.x + (1.f - z) * hh; }
    { float z = sigmoid_f(x1z.y + x2z.y); float r = sigmoid_f(x1r.y + x2r.y);
      float hh = tanhf(x1h.y + r * x2h.y); o.y = z * hv.y + (1.f - z) * hh; }
    { float z = sigmoid_f(x1z.z + x2z.z); float r = sigmoid_f(x1r.z + x2r.z);
      float hh = tanhf(x1h.z + r * x2h.z); o.z = z * hv.z + (1.f - z) * hh; }
    { float z = sigmoid_f(x1z.w + x2z.w); float r = sigmoid_f(x1r.w + x2r.w);
      float hh = tanhf(x1h.w + r * x2h.w); o.w = z * hv.w + (1.f - z) * hh; }
    *(float4*)(h + b128) = o;
}

// ---------------- Graph pooling ----------------
__global__ void pool_kernel(const float* __restrict__ h, const int* __restrict__ gids,
                            float* __restrict__ pool, int E)
{
    int i = blockIdx.x * blockDim.x + threadIdx.x;
    if (i >= E * 32) return;
    int e = i >> 5;
    int q = i & 31;
    int g = gids[e];
    float4 v = *(const float4*)(h + (size_t)e * 128 + q * 4);
    float* dst = pool + (size_t)g * 128 + q * 4;
    asm volatile("red.global.add.v4.f32 [%0], {%1,%2,%3,%4};"
                 :: "l"(dst), "f"(v.x), "f"(v.y), "f"(v.z), "f"(v.w) : "memory");
}

// ---------------- Final readout ----------------
__global__ void final_kernel(const float* __restrict__ h2, const float* __restrict__ W3,
                             const float* __restrict__ b3, float* __restrict__ out, int G)
{
    int w = (blockIdx.x * blockDim.x + threadIdx.x) >> 5;
    int lane = threadIdx.x & 31;
    if (w >= G) return;
    float s = 0.f;
    #pragma unroll
    for (int k = 0; k < 8; k++) {
        int j = k * 32 + lane;
        s = fmaf(h2[(size_t)w * 256 + j], W3[j], s);
    }
    #pragma unroll
    for (int off = 16; off > 0; off >>= 1)
        s += __shfl_xor_sync(0xffffffffu, s, off);
    if (lane == 0) out[w] = s + b3[0];
}

// ---------------- Host orchestration ----------------
extern "C" void kernel_launch(void* const* d_in, const int* in_sizes, int n_in,
                              void* d_out, int out_size)
{
    int o = (n_in >= 16) ? 0 : -1;

    const float* link_state = (const float*)d_in[0];
    const int*   gids       = (const int*)d_in[1];
    const int*   first      = (const int*)d_in[2];
    const int*   second     = (const int*)d_in[3];
    const float* W_msg      = (const float*)d_in[5 + o];
    const float* b_msg      = (const float*)d_in[6 + o];
    const float* gru_k      = (const float*)d_in[7 + o];
    const float* gru_rk     = (const float*)d_in[8 + o];
    const float* gru_b      = (const float*)d_in[9 + o];
    const float* W1         = (const float*)d_in[10 + o];
    const float* b1         = (const float*)d_in[11 + o];
    const float* W2         = (const float*)d_in[12 + o];
    const float* b2         = (const float*)d_in[13 + o];
    const float* W3         = (const float*)d_in[14 + o];
    const float* b3         = (const float*)d_in[15 + o];

    const int E = in_sizes[1];
    const int P = in_sizes[2];
    const int G = out_size;

    float *h, *agg, *UV, *X1, *X2, *pool, *r1, *r2, *b256;
    __half *WtHi, *WtLo;
    int *off, *cur, *pfirst, *blk;
    cudaGetSymbolAddress((void**)&h,    d_h);
    cudaGetSymbolAddress((void**)&agg,  d_agg);
    cudaGetSymbolAddress((void**)&UV,   d_UV);
    cudaGetSymbolAddress((void**)&X1,   d_X1);
    cudaGetSymbolAddress((void**)&X2,   d_X2);
    cudaGetSymbolAddress((void**)&pool, d_pool);
    cudaGetSymbolAddress((void**)&r1,   d_r1);
    cudaGetSymbolAddress((void**)&r2,   d_r2);
    cudaGetSymbolAddress((void**)&b256, d_b256);
    cudaGetSymbolAddress((void**)&WtHi, d_WtHi);
    cudaGetSymbolAddress((void**)&WtLo, d_WtLo);
    cudaGetSymbolAddress((void**)&off,    d_off);
    cudaGetSymbolAddress((void**)&cur,    d_cur);
    cudaGetSymbolAddress((void**)&pfirst, d_pfirst);
    cudaGetSymbolAddress((void**)&blk,    d_blk);

    cudaFuncSetAttribute(mma_gemm<true>,  cudaFuncAttributeMaxDynamicSharedMemorySize, SMEM_SZ);

    // side stream + events (created once, pre-capture)
    static cudaStream_t s1 = nullptr;
    static cudaEvent_t ev_boot = nullptr, ev_uv = nullptr, ev_x2 = nullptr,
                       ev_gA = nullptr, ev_gB = nullptr;
    if (s1 == nullptr) {
        cudaStreamCreateWithFlags(&s1, cudaStreamNonBlocking);
        cudaEventCreateWithFlags(&ev_boot, cudaEventDisableTiming);
        cudaEventCreateWithFlags(&ev_uv,   cudaEventDisableTiming);
        cudaEventCreateWithFlags(&ev_x2,   cudaEventDisableTiming);
        cudaEventCreateWithFlags(&ev_gA,   cudaEventDisableTiming);
        cudaEventCreateWithFlags(&ev_gB,   cudaEventDisableTiming);
    }

    const __half* WkHi  = WtHi;              const __half* WkLo  = WtLo;
    const __half* WrkHi = WtHi + 384 * 128;  const __half* WrkLo = WtLo + 384 * 128;
    const __half* WuvHi = WtHi + 768 * 128;  const __half* WuvLo = WtLo + 768 * 128;

    const int mb = (E + 95) / 96;
    // half split, aligned to 96 rows
    const int Eh = ((E / 2 + 95) / 96) * 96 < E ? ((E / 2 + 95) / 96) * 96 : E;
    const int mbA = (Eh + 95) / 96;
    const int mbB = (E - Eh + 95) / 96;
    const int nscan = E + 1;
    const int nblks = (nscan + 1023) / 1024;

    // ---- one-time prep (stream 0) ----
    prep_weights<<<(1024 * 128 + 255) / 256, 256>>>(gru_k, gru_rk, W_msg, b_msg, WtHi, WtLo, b256);
    cudaMemcpyAsync(h, link_state, (size_t)E * DIM * sizeof(float), cudaMemcpyDeviceToDevice);
    cudaMemsetAsync(off, 0, (size_t)nscan * sizeof(int));
    k_hist<<<(P + 255) / 256, 256>>>(second, off, P);
    k_scan1<<<nblks, 1024>>>(off, blk, nscan);
    k_scan2<<<1, 1024>>>(blk, nblks);
    k_scan3<<<nblks, 1024>>>(off, blk, cur, nscan, E);
    k_scatter<<<(P + 255) / 256, 256>>>(first, second, cur, pfirst, P);
    cudaEventRecord(ev_boot, 0);

    for (int t = 0; t < TSTEPS; t++) {
        // --- stream 1: X2 = h @ Wrk + b (needs full h) ---
        if (t == 0) cudaStreamWaitEvent(s1, ev_boot, 0);
        else        cudaStreamWaitEvent(s1, ev_gA, 0);      // h[0,Eh) from gatesA (s0); h[Eh,E) same-stream
        mma_gemm<true><<<dim3(mb, 3), 256, SMEM_SZ, s1>>>(h, WrkHi, WrkLo, gru_b + 384, X2, E, 384);
        cudaEventRecord(ev_x2, s1);

        // --- stream 0: UV (needs full h) ---
        if (t > 0) cudaStreamWaitEvent(0, ev_gB, 0);        // h[Eh,E) from gatesB (s1)
        mma_gemm<true><<<dim3(mb, 2), 256, SMEM_SZ>>>(h, WuvHi, WuvLo, b256, UV, E, 256);
        cudaEventRecord(ev_uv, 0);

        // --- seg halves ---
        seg_msg<<<(Eh + 7) / 8, 256>>>(UV, off, pfirst, agg, 0, Eh);               // s0
        cudaStreamWaitEvent(s1, ev_uv, 0);
        seg_msg<<<(E - Eh + 7) / 8, 256, 0, s1>>>(UV, off, pfirst, agg, Eh, E);    // s1

        // --- X1 halves ---
        mma_gemm<true><<<dim3(mbA, 3), 256, SMEM_SZ>>>(agg, WkHi, WkLo, gru_b, X1, Eh, 384);
        mma_gemm<true><<<dim3(mbB, 3), 256, SMEM_SZ, s1>>>(agg + (size_t)Eh * 128, WkHi, WkLo, gru_b,
                                                           X1 + (size_t)Eh * 384, E - Eh, 384);

        // --- gates halves ---
        cudaStreamWaitEvent(0, ev_x2, 0);                    // gatesA needs X2 (s1)
        gates_kernel<<<((Eh) * 32 + 255) / 256, 256>>>(X1, X2, h, 0, Eh);
        cudaEventRecord(ev_gA, 0);
        gates_kernel<<<((E - Eh) * 32 + 255) / 256, 256, 0, s1>>>(X1, X2, h, Eh, E);  // X2+X1B same-stream
        cudaEventRecord(ev_gB, s1);
    }

    // readout (stream 0) — needs h[Eh,E) from gatesB
    cudaStreamWaitEvent(0, ev_gB, 0);
    cudaMemsetAsync(pool, 0, (size_t)G * DIM * sizeof(float));
    pool_kernel<<<(E * 32 + 255) / 256, 256>>>(h, gids, pool, E);
    const int gblocks = (G + 127) / 128;
    sgemm_kernel<true, true><<<dim3(gblocks, 2), 256>>>(pool, W1, b1, r1, G, 256, 128);
    sgemm_kernel<true, true><<<dim3(gblocks, 2), 256>>>(r1, W2, b2, r2, G, 256, 256);
    final_kernel<<<(G * 32 + 255) / 256, 256>>>(r2, W3, b3, (float*)d_out, G);
}